// round 14
// baseline (speedup 1.0000x reference)
#include <cuda_runtime.h>

#define BB 16
#define HH 512
#define WW 512
#define NPAIR (HH / 2)         // 256 two-row chunks per column

// exclusive column-prefix of dg_y at 2-row granularity: g_tab[b][pair][w]
__device__ float g_tab[(size_t)BB * NPAIR * WW];

__device__ __forceinline__ float dgf(float t) {
    return 2.0f / (1.0f + __expf(-t));   // c=2 logistic
}

// ---------------------------------------------------------------------------
// Kernel 1: 2-row-granularity exclusive column prefix of dg_y.
// Block: 512 thr = 8 float4-lanes (16 w) x 64 segs of 8 rows (4 pairs).
// Grid: BB * (WW/16) = 512 blocks.
// ---------------------------------------------------------------------------
__global__ void __launch_bounds__(512) tab_kernel(const float4* __restrict__ dg4) {
    __shared__ float segsum[64][16];
    __shared__ float segoff[64][16];

    const int b   = blockIdx.x >> 5;            // WW/16 = 32 tiles per batch
    const int w0  = (blockIdx.x & 31) * 16;
    const int ln  = threadIdx.x & 7;            // float4 lane: 2 columns
    const int seg = threadIdx.x >> 3;           // 0..63, 8 rows each
    const int h0  = seg * 8;
    const int wA  = w0 + 2 * ln;                // even column
    const int f4c = wA >> 1;                    // float4 col within row (256/row)

    float csA[4], csB[4];
    float totA = 0.f, totB = 0.f;
    #pragma unroll
    for (int c = 0; c < 4; c++) {
        const float4 r0 = __ldg(&dg4[(size_t)(b * HH + h0 + 2 * c    ) * (WW / 2) + f4c]);
        const float4 r1 = __ldg(&dg4[(size_t)(b * HH + h0 + 2 * c + 1) * (WW / 2) + f4c]);
        const float sA = dgf(r0.y) + dgf(r1.y); // col wA:   (x,y) in .x,.y
        const float sB = dgf(r0.w) + dgf(r1.w); // col wA+1: (x,y) in .z,.w
        csA[c] = sA;  csB[c] = sB;
        totA += sA;   totB += sB;
    }
    segsum[seg][2 * ln]     = totA;
    segsum[seg][2 * ln + 1] = totB;
    __syncthreads();

    if (threadIdx.x < 16) {
        float a = 0.f;
        #pragma unroll
        for (int s2 = 0; s2 < 64; s2++) {
            float t = segsum[s2][threadIdx.x];
            segoff[s2][threadIdx.x] = a;        // exclusive seg prefix
            a += t;
        }
    }
    __syncthreads();

    float aA = segoff[seg][2 * ln];
    float aB = segoff[seg][2 * ln + 1];
    float2* t = reinterpret_cast<float2*>(g_tab + ((size_t)b * NPAIR + seg * 4) * WW + wA);
    #pragma unroll
    for (int c = 0; c < 4; c++) {
        t[(size_t)c * (WW / 2)] = make_float2(aA, aB);  // exclusive pair prefix
        aA += csA[c];
        aB += csB[c];
    }
}

// ---------------------------------------------------------------------------
// Kernel 2: grid only. 2 rows per block: block scan of dg_x -> x_s,
// y_s from pair table + in-register dg_y, affine, grid3 smem-staged
// coalesced float4 stores.
// Grid: BB*HH/2 = 4096 blocks of 512 threads.
// ---------------------------------------------------------------------------
__global__ void __launch_bounds__(512) grid_kernel(
    const float2* __restrict__ defgrad2,
    const float*  __restrict__ affine,
    float*        __restrict__ grid3)
{
    __shared__ float g3[2 * WW * 3];           // 12 KB staging
    __shared__ float wsum[2][16];

    const int b  = blockIdx.x >> 8;            // / NPAIR
    const int hp = blockIdx.x & (NPAIR - 1);
    const int h0 = hp * 2;
    const int w    = threadIdx.x;
    const int lane = w & 31;
    const int warp = w >> 5;

    const size_t row0 = ((size_t)b * HH + h0) * WW;
    const size_t row1 = row0 + WW;

    const float2 dgA  = __ldg(defgrad2 + row0 + w);
    const float2 dgB  = __ldg(defgrad2 + row1 + w);
    const float  yoff = g_tab[((size_t)b * NPAIR + hp) * WW + w];

    const float* A = affine + b * 9;
    const float a0 = __ldg(A + 0) + 1.f, a1 = __ldg(A + 1),       a2 = __ldg(A + 2);
    const float a3 = __ldg(A + 3),       a4 = __ldg(A + 4) + 1.f, a5 = __ldg(A + 5);
    const float a6 = __ldg(A + 6),       a7 = __ldg(A + 7),       a8 = __ldg(A + 8) + 1.f;

    float v0 = dgf(dgA.x);
    float v1 = dgf(dgB.x);
    const float ys0 = yoff + dgf(dgA.y);
    const float ys1 = ys0  + dgf(dgB.y);

    #pragma unroll
    for (int o = 1; o < 32; o <<= 1) {
        float n0 = __shfl_up_sync(0xffffffffu, v0, o);
        float n1 = __shfl_up_sync(0xffffffffu, v1, o);
        if (lane >= o) { v0 += n0; v1 += n1; }
    }
    if (lane == 31) { wsum[0][warp] = v0; wsum[1][warp] = v1; }
    __syncthreads();
    if (threadIdx.x < 32) {
        const int g = threadIdx.x >> 4, i = threadIdx.x & 15;
        float s = wsum[g][i];
        #pragma unroll
        for (int o = 1; o < 16; o <<= 1) {
            float n = __shfl_up_sync(0xffffffffu, s, o, 16);
            if (i >= o) s += n;
        }
        wsum[g][i] = s;
    }
    __syncthreads();
    const float xs0 = v0 + (warp ? wsum[0][warp - 1] : 0.f);
    const float xs1 = v1 + (warp ? wsum[1][warp - 1] : 0.f);

    g3[w * 3 + 0]          = a0 * xs0 + a1 * ys0 + a2;
    g3[w * 3 + 1]          = a3 * xs0 + a4 * ys0 + a5;
    g3[w * 3 + 2]          = a6 * xs0 + a7 * ys0 + a8;
    g3[WW * 3 + w * 3 + 0] = a0 * xs1 + a1 * ys1 + a2;
    g3[WW * 3 + w * 3 + 1] = a3 * xs1 + a4 * ys1 + a5;
    g3[WW * 3 + w * 3 + 2] = a6 * xs1 + a7 * ys1 + a8;
    __syncthreads();

    // 2 rows * 512 * 3 floats = 768 float4 = 512 + 256
    float4* dst = reinterpret_cast<float4*>(grid3 + row0 * 3);
    const float4* src = reinterpret_cast<const float4*>(g3);
    dst[threadIdx.x] = src[threadIdx.x];
    if (threadIdx.x < 256)
        dst[threadIdx.x + 512] = src[threadIdx.x + 512];
}

// ---------------------------------------------------------------------------
// Kernel 3: gather with 2 LANES PER PIXEL. Lane pair (2i,2i+1) handles pixel
// i: even lane loads the x0 column's top+bottom corners, odd lane the x1
// column's. Left/right corners of a pixel usually share a 128B line, so each
// load instruction now covers what previously took two -> ~2x fewer L1
// wavefronts (the measured bottleneck). Halves combined via shfl_xor(1);
// even lane stores.
// Grid: BB*HH*WW*2 / 256 = 32768 blocks of 256 threads.
// ---------------------------------------------------------------------------
__global__ void __launch_bounds__(256) gather_kernel(
    const float4* __restrict__ im4,
    const float*  __restrict__ grid3,
    float4*       __restrict__ out4)
{
    const int t    = blockIdx.x * 256 + threadIdx.x;   // half-pixel id
    const int p    = t >> 1;                           // pixel id
    const int side = t & 1;                            // 0 = x0 column, 1 = x1
    const int b    = p >> 18;                          // / (512*512)

    const float x = __ldg(grid3 + (size_t)p * 3);
    const float y = __ldg(grid3 + (size_t)p * 3 + 1);

    const int fx = (int)floorf(x);
    const int fy = (int)floorf(y);
    const int x0 = min(max(fx,     0), WW - 1);
    const int x1 = min(max(fx + 1, 0), WW - 1);
    const int y0 = min(max(fy,     0), HH - 1);
    const int y1 = min(max(fy + 1, 0), HH - 1);

    const int xs = side ? x1 : x0;

    const float4* imb = im4 + ((size_t)b << 18);
    const float4 T = __ldg(&imb[(size_t)y0 * WW + xs]);   // top corner
    const float4 B = __ldg(&imb[(size_t)y1 * WW + xs]);   // bottom corner

    const float wx   = side ? (x - (float)x0) : ((float)x1 - x);
    const float wtop = wx * ((float)y1 - y);
    const float wbot = wx * (y - (float)y0);

    float4 part;
    part.x = wtop * T.x + wbot * B.x;
    part.y = wtop * T.y + wbot * B.y;
    part.z = wtop * T.z + wbot * B.z;
    part.w = wtop * T.w + wbot * B.w;

    // combine the pair's halves
    float4 o;
    o.x = part.x + __shfl_xor_sync(0xffffffffu, part.x, 1);
    o.y = part.y + __shfl_xor_sync(0xffffffffu, part.y, 1);
    o.z = part.z + __shfl_xor_sync(0xffffffffu, part.z, 1);
    o.w = part.w + __shfl_xor_sync(0xffffffffu, part.w, 1);

    if (side == 0) out4[p] = o;
}

// ---------------------------------------------------------------------------
extern "C" void kernel_launch(void* const* d_in, const int* in_sizes, int n_in,
                              void* d_out, int out_size) {
    const float4* im4      = (const float4*)d_in[0];   // [16,512,512,4] f32
    const float2* defgrad2 = (const float2*)d_in[1];   // [16,512,512,2] f32
    const float*  affine   = (const float*)d_in[2];    // [16,9] f32

    float* out   = (float*)d_out;
    float* grid3 = out + (size_t)in_sizes[0];          // out has im's element count

    tab_kernel<<<BB * (WW / 16), 512>>>((const float4*)defgrad2);
    grid_kernel<<<(unsigned)(BB * HH / 2), 512>>>(defgrad2, affine, grid3);
    gather_kernel<<<(unsigned)(BB * HH * WW * 2 / 256), 256>>>(im4, grid3, (float4*)out);
}

// round 16
// speedup vs baseline: 1.0078x; 1.0078x over previous
#include <cuda_runtime.h>

#define BB 16
#define HH 512
#define WW 512
#define NPAIR (HH / 2)         // 256 two-row chunks per column

// exclusive column-prefix of dg_y at 2-row granularity: g_tab[b][pair][w]
__device__ float g_tab[(size_t)BB * NPAIR * WW];

__device__ __forceinline__ float dgf(float t) {
    return 2.0f / (1.0f + __expf(-t));   // c=2 logistic
}

// ---------------------------------------------------------------------------
// Kernel 1: 2-row-granularity exclusive column prefix of dg_y.
// Block: 256 thr = 4 float4-lanes (8 w) x 64 segs of 8 rows (4 pairs).
// Grid: BB * (WW/8) = 1024 blocks -> 6.9 blocks/SM, small wave tail.
// ---------------------------------------------------------------------------
__global__ void __launch_bounds__(256) tab_kernel(const float4* __restrict__ dg4) {
    __shared__ float segsum[64][8];
    __shared__ float segoff[64][8];

    const int b   = blockIdx.x >> 6;            // WW/8 = 64 tiles per batch
    const int w0  = (blockIdx.x & 63) * 8;
    const int ln  = threadIdx.x & 3;            // float4 lane: 2 columns
    const int seg = threadIdx.x >> 2;           // 0..63, 8 rows each
    const int h0  = seg * 8;
    const int wA  = w0 + 2 * ln;                // even column
    const int f4c = wA >> 1;                    // float4 col within row (256/row)

    float csA[4], csB[4];
    float totA = 0.f, totB = 0.f;
    #pragma unroll
    for (int c = 0; c < 4; c++) {
        const float4 r0 = __ldg(&dg4[(size_t)(b * HH + h0 + 2 * c    ) * (WW / 2) + f4c]);
        const float4 r1 = __ldg(&dg4[(size_t)(b * HH + h0 + 2 * c + 1) * (WW / 2) + f4c]);
        const float sA = dgf(r0.y) + dgf(r1.y); // col wA:   (x,y) in .x,.y
        const float sB = dgf(r0.w) + dgf(r1.w); // col wA+1: (x,y) in .z,.w
        csA[c] = sA;  csB[c] = sB;
        totA += sA;   totB += sB;
    }
    segsum[seg][2 * ln]     = totA;
    segsum[seg][2 * ln + 1] = totB;
    __syncthreads();

    if (threadIdx.x < 8) {
        float a = 0.f;
        #pragma unroll
        for (int s2 = 0; s2 < 64; s2++) {
            float t = segsum[s2][threadIdx.x];
            segoff[s2][threadIdx.x] = a;        // exclusive seg prefix
            a += t;
        }
    }
    __syncthreads();

    float aA = segoff[seg][2 * ln];
    float aB = segoff[seg][2 * ln + 1];
    float2* t = reinterpret_cast<float2*>(g_tab + ((size_t)b * NPAIR + seg * 4) * WW + wA);
    #pragma unroll
    for (int c = 0; c < 4; c++) {
        t[(size_t)c * (WW / 2)] = make_float2(aA, aB);  // exclusive pair prefix
        aA += csA[c];
        aB += csB[c];
    }
}

// ---------------------------------------------------------------------------
// Kernel 2: grid only. 2 rows per block: block scan of dg_x -> x_s,
// y_s from pair table + in-register dg_y, affine, grid3 smem-staged
// coalesced float4 stores.
// Grid: BB*HH/2 = 4096 blocks of 512 threads.
// ---------------------------------------------------------------------------
__global__ void __launch_bounds__(512) grid_kernel(
    const float2* __restrict__ defgrad2,
    const float*  __restrict__ affine,
    float*        __restrict__ grid3)
{
    __shared__ float g3[2 * WW * 3];           // 12 KB staging
    __shared__ float wsum[2][16];

    const int b  = blockIdx.x >> 8;            // / NPAIR
    const int hp = blockIdx.x & (NPAIR - 1);
    const int h0 = hp * 2;
    const int w    = threadIdx.x;
    const int lane = w & 31;
    const int warp = w >> 5;

    const size_t row0 = ((size_t)b * HH + h0) * WW;
    const size_t row1 = row0 + WW;

    const float2 dgA  = __ldg(defgrad2 + row0 + w);
    const float2 dgB  = __ldg(defgrad2 + row1 + w);
    const float  yoff = g_tab[((size_t)b * NPAIR + hp) * WW + w];

    const float* A = affine + b * 9;
    const float a0 = __ldg(A + 0) + 1.f, a1 = __ldg(A + 1),       a2 = __ldg(A + 2);
    const float a3 = __ldg(A + 3),       a4 = __ldg(A + 4) + 1.f, a5 = __ldg(A + 5);
    const float a6 = __ldg(A + 6),       a7 = __ldg(A + 7),       a8 = __ldg(A + 8) + 1.f;

    float v0 = dgf(dgA.x);
    float v1 = dgf(dgB.x);
    const float ys0 = yoff + dgf(dgA.y);
    const float ys1 = ys0  + dgf(dgB.y);

    #pragma unroll
    for (int o = 1; o < 32; o <<= 1) {
        float n0 = __shfl_up_sync(0xffffffffu, v0, o);
        float n1 = __shfl_up_sync(0xffffffffu, v1, o);
        if (lane >= o) { v0 += n0; v1 += n1; }
    }
    if (lane == 31) { wsum[0][warp] = v0; wsum[1][warp] = v1; }
    __syncthreads();
    if (threadIdx.x < 32) {
        const int g = threadIdx.x >> 4, i = threadIdx.x & 15;
        float s = wsum[g][i];
        #pragma unroll
        for (int o = 1; o < 16; o <<= 1) {
            float n = __shfl_up_sync(0xffffffffu, s, o, 16);
            if (i >= o) s += n;
        }
        wsum[g][i] = s;
    }
    __syncthreads();
    const float xs0 = v0 + (warp ? wsum[0][warp - 1] : 0.f);
    const float xs1 = v1 + (warp ? wsum[1][warp - 1] : 0.f);

    g3[w * 3 + 0]          = a0 * xs0 + a1 * ys0 + a2;
    g3[w * 3 + 1]          = a3 * xs0 + a4 * ys0 + a5;
    g3[w * 3 + 2]          = a6 * xs0 + a7 * ys0 + a8;
    g3[WW * 3 + w * 3 + 0] = a0 * xs1 + a1 * ys1 + a2;
    g3[WW * 3 + w * 3 + 1] = a3 * xs1 + a4 * ys1 + a5;
    g3[WW * 3 + w * 3 + 2] = a6 * xs1 + a7 * ys1 + a8;
    __syncthreads();

    // 2 rows * 512 * 3 floats = 768 float4 = 512 + 256
    float4* dst = reinterpret_cast<float4*>(grid3 + row0 * 3);
    const float4* src = reinterpret_cast<const float4*>(g3);
    dst[threadIdx.x] = src[threadIdx.x];
    if (threadIdx.x < 256)
        dst[threadIdx.x + 512] = src[threadIdx.x + 512];
}

// ---------------------------------------------------------------------------
// Kernel 3: gather, 2 vertically-adjacent pixels per thread, ALL 8 corner
// loads issued unconditionally up front (best measured variant, R13).
// Grid: BB*(HH/2)*WW / 256 = 8192 blocks of 256 threads.
// ---------------------------------------------------------------------------
__global__ void __launch_bounds__(256, 5) gather_kernel(
    const float4* __restrict__ im4,
    const float*  __restrict__ grid3,
    float4*       __restrict__ out4)
{
    const int p   = blockIdx.x * 256 + threadIdx.x;  // pair id
    const int b   = p >> 17;                         // / (256*512)
    const int rem = p & 131071;
    const int hp  = rem >> 9;
    const int w   = rem & 511;

    const size_t idx0 = ((size_t)(b * HH + 2 * hp)) * WW + w;
    const size_t idx1 = idx0 + WW;

    const float x_0 = __ldg(grid3 + idx0 * 3);
    const float y_0 = __ldg(grid3 + idx0 * 3 + 1);
    const float x_1 = __ldg(grid3 + idx1 * 3);
    const float y_1 = __ldg(grid3 + idx1 * 3 + 1);

    const float4* imb = im4 + ((size_t)b << 18);

    const int fx0 = (int)floorf(x_0), fy0 = (int)floorf(y_0);
    const int fx1 = (int)floorf(x_1), fy1 = (int)floorf(y_1);
    const int X0 = min(max(fx0,     0), WW - 1);
    const int X1 = min(max(fx0 + 1, 0), WW - 1);
    const int Y0 = min(max(fy0,     0), HH - 1);
    const int Y1 = min(max(fy0 + 1, 0), HH - 1);
    const int U0 = min(max(fx1,     0), WW - 1);
    const int U1 = min(max(fx1 + 1, 0), WW - 1);
    const int V0 = min(max(fy1,     0), HH - 1);
    const int V1 = min(max(fy1 + 1, 0), HH - 1);

    // 8 independent gathers in flight
    const float4 Ia = __ldg(&imb[(size_t)Y0 * WW + X0]);
    const float4 Ib = __ldg(&imb[(size_t)Y1 * WW + X0]);
    const float4 Ic = __ldg(&imb[(size_t)Y0 * WW + X1]);
    const float4 Id = __ldg(&imb[(size_t)Y1 * WW + X1]);
    const float4 Ja = __ldg(&imb[(size_t)V0 * WW + U0]);
    const float4 Jb = __ldg(&imb[(size_t)V1 * WW + U0]);
    const float4 Jc = __ldg(&imb[(size_t)V0 * WW + U1]);
    const float4 Jd = __ldg(&imb[(size_t)V1 * WW + U1]);

    {
        const float wx1 = (float)X1 - x_0, wx0 = x_0 - (float)X0;
        const float wy1 = (float)Y1 - y_0, wy0 = y_0 - (float)Y0;
        const float wa = wx1 * wy1, wb = wx1 * wy0, wc = wx0 * wy1, wd = wx0 * wy0;
        float4 o;
        o.x = wa * Ia.x + wb * Ib.x + wc * Ic.x + wd * Id.x;
        o.y = wa * Ia.y + wb * Ib.y + wc * Ic.y + wd * Id.y;
        o.z = wa * Ia.z + wb * Ib.z + wc * Ic.z + wd * Id.z;
        o.w = wa * Ia.w + wb * Ib.w + wc * Ic.w + wd * Id.w;
        out4[idx0] = o;
    }
    {
        const float wx1 = (float)U1 - x_1, wx0 = x_1 - (float)U0;
        const float wy1 = (float)V1 - y_1, wy0 = y_1 - (float)V0;
        const float wa = wx1 * wy1, wb = wx1 * wy0, wc = wx0 * wy1, wd = wx0 * wy0;
        float4 o;
        o.x = wa * Ja.x + wb * Jb.x + wc * Jc.x + wd * Jd.x;
        o.y = wa * Ja.y + wb * Jb.y + wc * Jc.y + wd * Jd.y;
        o.z = wa * Ja.z + wb * Jb.z + wc * Jc.z + wd * Jd.z;
        o.w = wa * Ja.w + wb * Jb.w + wc * Jc.w + wd * Jd.w;
        out4[idx1] = o;
    }
}

// ---------------------------------------------------------------------------
extern "C" void kernel_launch(void* const* d_in, const int* in_sizes, int n_in,
                              void* d_out, int out_size) {
    const float4* im4      = (const float4*)d_in[0];   // [16,512,512,4] f32
    const float2* defgrad2 = (const float2*)d_in[1];   // [16,512,512,2] f32
    const float*  affine   = (const float*)d_in[2];    // [16,9] f32

    float* out   = (float*)d_out;
    float* grid3 = out + (size_t)in_sizes[0];          // out has im's element count

    tab_kernel<<<BB * (WW / 8), 256>>>((const float4*)defgrad2);
    grid_kernel<<<(unsigned)(BB * HH / 2), 512>>>(defgrad2, affine, grid3);
    gather_kernel<<<(unsigned)(BB * NPAIR * WW / 256), 256>>>(im4, grid3, (float4*)out);
}

// round 17
// speedup vs baseline: 1.0586x; 1.0504x over previous
#include <cuda_runtime.h>

#define BB 16
#define HH 512
#define WW 512
#define NCHK (HH / 8)          // 64 eight-row chunks per column

// exclusive column-prefix of dg_y at 8-row granularity: g_tab[b][chunk][w]
__device__ float g_tab[(size_t)BB * NCHK * WW];

__device__ __forceinline__ float dgf(float t) {
    return 2.0f / (1.0f + __expf(-t));   // c=2 logistic
}

// ---------------------------------------------------------------------------
// Kernel 1: 8-row-granularity exclusive column prefix of dg_y.
// Block: 256 thr = 4 float4-lanes (8 w) x 64 segs of 8 rows.
// Each thread sums 8 rows for 2 columns; t<8 does the 64-seg serial prefix;
// one float2 write per thread. Table is only 2.1 MB.
// Grid: BB * (WW/8) = 1024 blocks.
// ---------------------------------------------------------------------------
__global__ void __launch_bounds__(256) tab_kernel(const float4* __restrict__ dg4) {
    __shared__ float segsum[NCHK][8];
    __shared__ float segoff[NCHK][8];

    const int b   = blockIdx.x >> 6;            // WW/8 = 64 tiles per batch
    const int w0  = (blockIdx.x & 63) * 8;
    const int ln  = threadIdx.x & 3;            // float4 lane: 2 columns
    const int seg = threadIdx.x >> 2;           // 0..63, 8 rows each
    const int h0  = seg * 8;
    const int wA  = w0 + 2 * ln;                // even column
    const int f4c = wA >> 1;                    // float4 col within row (256/row)

    float totA = 0.f, totB = 0.f;
    #pragma unroll
    for (int c = 0; c < 4; c++) {
        const float4 r0 = __ldg(&dg4[(size_t)(b * HH + h0 + 2 * c    ) * (WW / 2) + f4c]);
        const float4 r1 = __ldg(&dg4[(size_t)(b * HH + h0 + 2 * c + 1) * (WW / 2) + f4c]);
        totA += dgf(r0.y) + dgf(r1.y);          // col wA:   (x,y) in .x,.y
        totB += dgf(r0.w) + dgf(r1.w);          // col wA+1: (x,y) in .z,.w
    }
    segsum[seg][2 * ln]     = totA;
    segsum[seg][2 * ln + 1] = totB;
    __syncthreads();

    if (threadIdx.x < 8) {
        float a = 0.f;
        #pragma unroll
        for (int s2 = 0; s2 < NCHK; s2++) {
            float t = segsum[s2][threadIdx.x];
            segoff[s2][threadIdx.x] = a;        // exclusive seg prefix
            a += t;
        }
    }
    __syncthreads();

    float2* t = reinterpret_cast<float2*>(g_tab + ((size_t)b * NCHK + seg) * WW + wA);
    *t = make_float2(segoff[seg][2 * ln], segoff[seg][2 * ln + 1]);
}

// ---------------------------------------------------------------------------
// Kernel 2: grid only, 8 rows per block. 8 parallel block scans of dg_x,
// ys from 8-row table + in-register dg_y accumulation, affine, grid3 staged
// 4 rows at a time in 24KB smem with coalesced float4 writebacks.
// No gathers here -> regs ~50, barriers amortized over 8 rows.
// Grid: BB*HH/8 = 1024 blocks of 512 threads.
// ---------------------------------------------------------------------------
__global__ void __launch_bounds__(512) grid_kernel(
    const float2* __restrict__ defgrad2,
    const float*  __restrict__ affine,
    float*        __restrict__ grid3)
{
    __shared__ float g3[4 * WW * 3];           // 24 KB staging (4 rows)
    __shared__ float wsum[8][16];

    const int b  = blockIdx.x >> 6;            // / NCHK
    const int hp = blockIdx.x & (NCHK - 1);
    const int h0 = hp * 8;
    const int w    = threadIdx.x;
    const int lane = w & 31;
    const int warp = w >> 5;

    const size_t row0 = ((size_t)b * HH + h0) * WW;

    // front-batched coalesced loads: 8 defgrad rows + table offset
    float2 d[8];
    #pragma unroll
    for (int r = 0; r < 8; r++)
        d[r] = __ldg(defgrad2 + row0 + (size_t)r * WW + w);
    const float yoff = g_tab[((size_t)b * NCHK + hp) * WW + w];

    const float* A = affine + b * 9;
    const float a0 = __ldg(A + 0) + 1.f, a1 = __ldg(A + 1),       a2 = __ldg(A + 2);
    const float a3 = __ldg(A + 3),       a4 = __ldg(A + 4) + 1.f, a5 = __ldg(A + 5);
    const float a6 = __ldg(A + 6),       a7 = __ldg(A + 7),       a8 = __ldg(A + 8) + 1.f;

    float v[8];
    #pragma unroll
    for (int r = 0; r < 8; r++) v[r] = dgf(d[r].x);

    // 8 parallel block-wide inclusive scans
    #pragma unroll
    for (int o = 1; o < 32; o <<= 1) {
        float n[8];
        #pragma unroll
        for (int r = 0; r < 8; r++) n[r] = __shfl_up_sync(0xffffffffu, v[r], o);
        if (lane >= o) {
            #pragma unroll
            for (int r = 0; r < 8; r++) v[r] += n[r];
        }
    }
    if (lane == 31) {
        #pragma unroll
        for (int r = 0; r < 8; r++) wsum[r][warp] = v[r];
    }
    __syncthreads();
    if (threadIdx.x < 128) {
        const int g = threadIdx.x >> 4, i = threadIdx.x & 15;
        float s = wsum[g][i];
        #pragma unroll
        for (int o = 1; o < 16; o <<= 1) {
            float n = __shfl_up_sync(0xffffffffu, s, o, 16);
            if (i >= o) s += n;
        }
        wsum[g][i] = s;
    }
    __syncthreads();
    float xs[8];
    #pragma unroll
    for (int r = 0; r < 8; r++)
        xs[r] = v[r] + (warp ? wsum[r][warp - 1] : 0.f);

    float acc = yoff;
    #pragma unroll
    for (int half = 0; half < 2; half++) {
        #pragma unroll
        for (int q = 0; q < 4; q++) {
            const int r = half * 4 + q;
            acc += dgf(d[r].y);                 // inclusive ys at row r
            const float ys = acc;
            const int s = q * (WW * 3) + w * 3;
            g3[s + 0] = a0 * xs[r] + a1 * ys + a2;
            g3[s + 1] = a3 * xs[r] + a4 * ys + a5;
            g3[s + 2] = a6 * xs[r] + a7 * ys + a8;
        }
        __syncthreads();
        // 4 rows * 512 * 3 floats = 6144 floats = 1536 float4 = 3 per thread
        float4* dst = reinterpret_cast<float4*>(
            grid3 + (row0 + (size_t)(half * 4) * WW) * 3);
        const float4* src = reinterpret_cast<const float4*>(g3);
        #pragma unroll
        for (int i = 0; i < 3; i++)
            dst[threadIdx.x + i * 512] = src[threadIdx.x + i * 512];
        if (half == 0) __syncthreads();        // protect g3 before re-staging
    }
}

// ---------------------------------------------------------------------------
// Kernel 3: gather, 2 vertically-adjacent pixels per thread, 8 corner loads
// in flight. Streaming hints: xy read + out store use evict-first so L2
// capacity is preserved for re-referenced im sectors.
// Grid: BB*(HH/2)*WW / 256 = 8192 blocks of 256 threads.
// ---------------------------------------------------------------------------
__global__ void __launch_bounds__(256, 5) gather_kernel(
    const float4* __restrict__ im4,
    const float*  __restrict__ grid3,
    float4*       __restrict__ out4)
{
    const int p   = blockIdx.x * 256 + threadIdx.x;  // pair id
    const int b   = p >> 17;                         // / (256*512)
    const int rem = p & 131071;
    const int hp  = rem >> 9;
    const int w   = rem & 511;

    const size_t idx0 = ((size_t)(b * HH + 2 * hp)) * WW + w;
    const size_t idx1 = idx0 + WW;

    const float x_0 = __ldcs(grid3 + idx0 * 3);
    const float y_0 = __ldcs(grid3 + idx0 * 3 + 1);
    const float x_1 = __ldcs(grid3 + idx1 * 3);
    const float y_1 = __ldcs(grid3 + idx1 * 3 + 1);

    const float4* imb = im4 + ((size_t)b << 18);

    const int fx0 = (int)floorf(x_0), fy0 = (int)floorf(y_0);
    const int fx1 = (int)floorf(x_1), fy1 = (int)floorf(y_1);
    const int X0 = min(max(fx0,     0), WW - 1);
    const int X1 = min(max(fx0 + 1, 0), WW - 1);
    const int Y0 = min(max(fy0,     0), HH - 1);
    const int Y1 = min(max(fy0 + 1, 0), HH - 1);
    const int U0 = min(max(fx1,     0), WW - 1);
    const int U1 = min(max(fx1 + 1, 0), WW - 1);
    const int V0 = min(max(fy1,     0), HH - 1);
    const int V1 = min(max(fy1 + 1, 0), HH - 1);

    // 8 independent gathers in flight
    const float4 Ia = __ldg(&imb[(size_t)Y0 * WW + X0]);
    const float4 Ib = __ldg(&imb[(size_t)Y1 * WW + X0]);
    const float4 Ic = __ldg(&imb[(size_t)Y0 * WW + X1]);
    const float4 Id = __ldg(&imb[(size_t)Y1 * WW + X1]);
    const float4 Ja = __ldg(&imb[(size_t)V0 * WW + U0]);
    const float4 Jb = __ldg(&imb[(size_t)V1 * WW + U0]);
    const float4 Jc = __ldg(&imb[(size_t)V0 * WW + U1]);
    const float4 Jd = __ldg(&imb[(size_t)V1 * WW + U1]);

    {
        const float wx1 = (float)X1 - x_0, wx0 = x_0 - (float)X0;
        const float wy1 = (float)Y1 - y_0, wy0 = y_0 - (float)Y0;
        const float wa = wx1 * wy1, wb = wx1 * wy0, wc = wx0 * wy1, wd = wx0 * wy0;
        float4 o;
        o.x = wa * Ia.x + wb * Ib.x + wc * Ic.x + wd * Id.x;
        o.y = wa * Ia.y + wb * Ib.y + wc * Ic.y + wd * Id.y;
        o.z = wa * Ia.z + wb * Ib.z + wc * Ic.z + wd * Id.z;
        o.w = wa * Ia.w + wb * Ib.w + wc * Ic.w + wd * Id.w;
        __stcs(&out4[idx0], o);
    }
    {
        const float wx1 = (float)U1 - x_1, wx0 = x_1 - (float)U0;
        const float wy1 = (float)V1 - y_1, wy0 = y_1 - (float)V0;
        const float wa = wx1 * wy1, wb = wx1 * wy0, wc = wx0 * wy1, wd = wx0 * wy0;
        float4 o;
        o.x = wa * Ja.x + wb * Jb.x + wc * Jc.x + wd * Jd.x;
        o.y = wa * Ja.y + wb * Jb.y + wc * Jc.y + wd * Jd.y;
        o.z = wa * Ja.z + wb * Jb.z + wc * Jc.z + wd * Jd.z;
        o.w = wa * Ja.w + wb * Jb.w + wc * Jc.w + wd * Jd.w;
        __stcs(&out4[idx1], o);
    }
}

// ---------------------------------------------------------------------------
extern "C" void kernel_launch(void* const* d_in, const int* in_sizes, int n_in,
                              void* d_out, int out_size) {
    const float4* im4      = (const float4*)d_in[0];   // [16,512,512,4] f32
    const float2* defgrad2 = (const float2*)d_in[1];   // [16,512,512,2] f32
    const float*  affine   = (const float*)d_in[2];    // [16,9] f32

    float* out   = (float*)d_out;
    float* grid3 = out + (size_t)in_sizes[0];          // out has im's element count

    tab_kernel<<<BB * (WW / 8), 256>>>((const float4*)defgrad2);
    grid_kernel<<<(unsigned)(BB * HH / 8), 512>>>(defgrad2, affine, grid3);
    gather_kernel<<<(unsigned)(BB * (HH / 2) * WW / 256), 256>>>(im4, grid3, (float4*)out);
}